// round 1
// baseline (speedup 1.0000x reference)
#include <cuda_runtime.h>
#include <math.h>

#define CC 768
#define NN 256
#define FF 512
#define BATCH 1024
#define ROWS_FINE 4096          // BATCH * 4
#define OUTROW 131073           // 1 + N*F
#define LOGF 6.238324625039508f // log(512)

// ---------------- scratch (no allocations allowed) ----------------
__device__ float g_xn[BATCH * CC];
__device__ float g_buf1[ROWS_FINE * CC];
__device__ float g_buf2[ROWS_FINE * CC];
__device__ float g_coarse[BATCH * NN];
__device__ int   g_idx[BATCH * 4];
__device__ float g_fine_in[ROWS_FINE * 2 * CC];
__device__ float g_fine[ROWS_FINE * FF];
__device__ float g_lse[ROWS_FINE];

__device__ __forceinline__ float gelu_tanh(float x) {
    float x3 = x * x * x;
    return 0.5f * x * (1.0f + tanhf(0.7978845608028654f * (x + 0.044715f * x3)));
}

// ---------------- LayerNorm(x) + no_op head ----------------
// one block (256 threads) per batch row; writes g_xn and out[b*OUTROW + 0]
__global__ void ln_noop_kernel(const float* __restrict__ x,
                               const float* __restrict__ gin,
                               const float* __restrict__ bin,
                               const float* __restrict__ nW,
                               const float* __restrict__ nb,
                               float* __restrict__ out) {
    int b = blockIdx.x, tid = threadIdx.x;
    const float* xr = x + (size_t)b * CC;
    __shared__ float red[256];
    float v[3];
    float s = 0.f, ss = 0.f;
#pragma unroll
    for (int i = 0; i < 3; i++) {
        v[i] = xr[tid + i * 256];
        s += v[i];
        ss += v[i] * v[i];
    }
    red[tid] = s; __syncthreads();
    for (int o = 128; o > 0; o >>= 1) { if (tid < o) red[tid] += red[tid + o]; __syncthreads(); }
    float mean = red[0] * (1.0f / CC);
    __syncthreads();
    red[tid] = ss; __syncthreads();
    for (int o = 128; o > 0; o >>= 1) { if (tid < o) red[tid] += red[tid + o]; __syncthreads(); }
    float var = red[0] * (1.0f / CC) - mean * mean;
    float rstd = rsqrtf(var + 1e-5f);
    __syncthreads();
    float dot = 0.f;
#pragma unroll
    for (int i = 0; i < 3; i++) {
        int c = tid + i * 256;
        float xn = (v[i] - mean) * rstd * gin[c] + bin[c];
        g_xn[(size_t)b * CC + c] = xn;
        dot += xn * nW[c];
    }
    red[tid] = dot; __syncthreads();
    for (int o = 128; o > 0; o >>= 1) { if (tid < o) red[tid] += red[tid + o]; __syncthreads(); }
    if (tid == 0) out[(size_t)b * OUTROW] = red[0] + nb[0];
}

// ---------------- SGEMM 128x128x8, 256 threads, 8x8 per thread ----------------
// C[M,N] = act(A[M,K] @ W[K,N] + bias[N]); A,W row-major. M%128==0, N%128==0, K%8==0.
template <bool GELU>
__global__ void __launch_bounds__(256, 2)
sgemm_kernel(const float* __restrict__ A, const float* __restrict__ W,
             const float* __restrict__ bias, float* __restrict__ C,
             int M, int N, int K) {
    __shared__ float As[8][128];
    __shared__ float Bs[8][128];
    int tid = threadIdx.x;
    int bx = blockIdx.x, by = blockIdx.y;
    int arow = tid >> 1, acol = (tid & 1) << 2;   // 128 rows x 8 cols, one float4/thread
    int brow = tid >> 5, bcol = (tid & 31) << 2;  // 8 rows x 128 cols
    const float* Ap = A + (size_t)(by * 128 + arow) * K + acol;
    const float* Wp = W + (size_t)brow * N + bx * 128 + bcol;
    int tx = tid & 15, ty = tid >> 4;
    float acc[8][8];
#pragma unroll
    for (int i = 0; i < 8; i++)
#pragma unroll
        for (int j = 0; j < 8; j++) acc[i][j] = 0.f;

    for (int k0 = 0; k0 < K; k0 += 8) {
        float4 av = *(const float4*)(Ap + k0);
        float4 bv = *(const float4*)(Wp + (size_t)k0 * N);
        As[acol + 0][arow] = av.x;
        As[acol + 1][arow] = av.y;
        As[acol + 2][arow] = av.z;
        As[acol + 3][arow] = av.w;
        *(float4*)&Bs[brow][bcol] = bv;
        __syncthreads();
#pragma unroll
        for (int kk = 0; kk < 8; kk++) {
            float4 a0 = *(const float4*)&As[kk][ty * 8];
            float4 a1 = *(const float4*)&As[kk][ty * 8 + 4];
            float4 b0 = *(const float4*)&Bs[kk][tx * 8];
            float4 b1 = *(const float4*)&Bs[kk][tx * 8 + 4];
            float ar[8] = {a0.x, a0.y, a0.z, a0.w, a1.x, a1.y, a1.z, a1.w};
            float br[8] = {b0.x, b0.y, b0.z, b0.w, b1.x, b1.y, b1.z, b1.w};
#pragma unroll
            for (int i = 0; i < 8; i++)
#pragma unroll
                for (int j = 0; j < 8; j++)
                    acc[i][j] = fmaf(ar[i], br[j], acc[i][j]);
        }
        __syncthreads();
    }
    int row0 = by * 128 + ty * 8, col0 = bx * 128 + tx * 8;
#pragma unroll
    for (int i = 0; i < 8; i++) {
        float* Cr = C + (size_t)(row0 + i) * N + col0;
#pragma unroll
        for (int j = 0; j < 8; j++) {
            float val = acc[i][j] + bias[col0 + j];
            if (GELU) val = gelu_tanh(val);
            Cr[j] = val;
        }
    }
}

// ---------------- top-4 of coarse row (256 values), one warp per row ----------------
__global__ void top4_kernel(const float* __restrict__ coarse, int* __restrict__ idx) {
    int warp = threadIdx.x >> 5, lane = threadIdx.x & 31;
    int row = blockIdx.x * 8 + warp;
    const float* cr = coarse + (size_t)row * NN;
    float v[8];
    int id[8];
#pragma unroll
    for (int i = 0; i < 8; i++) {
        id[i] = lane + i * 32;
        v[i] = cr[id[i]];
    }
#pragma unroll
    for (int r = 0; r < 4; r++) {
        float bv = -INFINITY;
        int bi = 1 << 30;
#pragma unroll
        for (int i = 0; i < 8; i++)
            if (v[i] > bv || (v[i] == bv && id[i] < bi)) { bv = v[i]; bi = id[i]; }
        for (int o = 16; o > 0; o >>= 1) {
            float ov = __shfl_xor_sync(0xffffffffu, bv, o);
            int oi = __shfl_xor_sync(0xffffffffu, bi, o);
            if (ov > bv || (ov == bv && oi < bi)) { bv = ov; bi = oi; }
        }
        if (lane == 0) idx[row * 4 + r] = bi;
#pragma unroll
        for (int i = 0; i < 8; i++)
            if (id[i] == bi) v[i] = -INFINITY;
    }
}

// ---------------- fine_in = concat(xn, LN(emb[idx])) ; one block per (b,k) row ----------------
__global__ void build_fine_kernel(const float* __restrict__ emb,
                                  const float* __restrict__ ge,
                                  const float* __restrict__ be) {
    int r = blockIdx.x, tid = threadIdx.x;
    int b = r >> 2;
    int n = g_idx[r];
    const float* er = emb + (size_t)n * CC;
    __shared__ float red[256];
    float v[3];
    float s = 0.f, ss = 0.f;
#pragma unroll
    for (int i = 0; i < 3; i++) {
        v[i] = er[tid + i * 256];
        s += v[i];
        ss += v[i] * v[i];
    }
    red[tid] = s; __syncthreads();
    for (int o = 128; o > 0; o >>= 1) { if (tid < o) red[tid] += red[tid + o]; __syncthreads(); }
    float mean = red[0] * (1.0f / CC);
    __syncthreads();
    red[tid] = ss; __syncthreads();
    for (int o = 128; o > 0; o >>= 1) { if (tid < o) red[tid] += red[tid + o]; __syncthreads(); }
    float var = red[0] * (1.0f / CC) - mean * mean;
    float rstd = rsqrtf(var + 1e-5f);
    float* fo = g_fine_in + (size_t)r * (2 * CC);
#pragma unroll
    for (int i = 0; i < 3; i++) {
        int c = tid + i * 256;
        fo[c] = g_xn[(size_t)b * CC + c];
        fo[CC + c] = (v[i] - mean) * rstd * ge[c] + be[c];
    }
}

// ---------------- logsumexp over fine rows (512), one block per row ----------------
__global__ void lse_kernel() {
    int r = blockIdx.x, tid = threadIdx.x;
    const float* fr = g_fine + (size_t)r * FF;
    __shared__ float red[256];
    float a = fr[tid], b2 = fr[tid + 256];
    red[tid] = fmaxf(a, b2); __syncthreads();
    for (int o = 128; o > 0; o >>= 1) { if (tid < o) red[tid] = fmaxf(red[tid], red[tid + o]); __syncthreads(); }
    float m = red[0];
    __syncthreads();
    red[tid] = expf(a - m) + expf(b2 - m); __syncthreads();
    for (int o = 128; o > 0; o >>= 1) { if (tid < o) red[tid] += red[tid + o]; __syncthreads(); }
    if (tid == 0) g_lse[r] = m + logf(red[0]);
}

// ---------------- scatter + permute + final write (537 MB) ----------------
// grid.x = 1024*16 ; each block writes 8192 contiguous output floats of one row
__global__ void output_kernel(float* __restrict__ out) {
    int b = blockIdx.x >> 4;
    int chunk = blockIdx.x & 15;
    int tid = threadIdx.x;
    __shared__ float sc[NN];
    __shared__ int sidx[4];
    __shared__ float slse[4];
    sc[tid] = g_coarse[(size_t)b * NN + tid];
    if (tid < 4) {
        sidx[tid] = g_idx[b * 4 + tid];
        slse[tid] = g_lse[b * 4 + tid];
    }
    __syncthreads();
    size_t obase = (size_t)b * OUTROW + 1;
#pragma unroll 4
    for (int it = 0; it < 32; it++) {
        int o = chunk * 8192 + it * 256 + tid;
        int ch = o >> 13, fh = (o >> 9) & 15, cw = (o >> 5) & 15, j = o & 31;
        int n = (ch << 4) + cw;
        int f = (fh << 5) + j;
        float v = sc[n] - LOGF;
#pragma unroll
        for (int k = 0; k < 4; k++)
            if (sidx[k] == n)
                v = sc[n] + g_fine[(size_t)(b * 4 + k) * FF + f] - slse[k];
        out[obase + o] = v;
    }
}

// ---------------- launch ----------------
extern "C" void kernel_launch(void* const* d_in, const int* in_sizes, int n_in,
                              void* d_out, int out_size) {
    (void)in_sizes; (void)n_in; (void)out_size;
    const float* x    = (const float*)d_in[0];
    const float* gin  = (const float*)d_in[1];
    const float* bin  = (const float*)d_in[2];
    const float* cW1  = (const float*)d_in[3];
    const float* cb1  = (const float*)d_in[4];
    const float* cW2  = (const float*)d_in[5];
    const float* cb2  = (const float*)d_in[6];
    const float* cW3  = (const float*)d_in[7];
    const float* cb3  = (const float*)d_in[8];
    const float* emb  = (const float*)d_in[9];
    const float* ge   = (const float*)d_in[10];
    const float* be   = (const float*)d_in[11];
    const float* fW1  = (const float*)d_in[12];
    const float* fb1  = (const float*)d_in[13];
    const float* fW2  = (const float*)d_in[14];
    const float* fb2  = (const float*)d_in[15];
    const float* fW3  = (const float*)d_in[16];
    const float* fb3  = (const float*)d_in[17];
    const float* nW   = (const float*)d_in[18];
    const float* nb   = (const float*)d_in[19];
    float* out = (float*)d_out;

    float *xn, *b1p, *b2p, *coarse, *fine_in, *fine;
    int* idxp;
    cudaGetSymbolAddress((void**)&xn, g_xn);
    cudaGetSymbolAddress((void**)&b1p, g_buf1);
    cudaGetSymbolAddress((void**)&b2p, g_buf2);
    cudaGetSymbolAddress((void**)&coarse, g_coarse);
    cudaGetSymbolAddress((void**)&idxp, g_idx);
    cudaGetSymbolAddress((void**)&fine_in, g_fine_in);
    cudaGetSymbolAddress((void**)&fine, g_fine);

    // 1. LN + no_op
    ln_noop_kernel<<<BATCH, 256>>>(x, gin, bin, nW, nb, out);

    // 2-4. coarse MLP
    sgemm_kernel<true><<<dim3(CC / 128, BATCH / 128), 256>>>(xn, cW1, cb1, b1p, BATCH, CC, CC);
    sgemm_kernel<true><<<dim3(CC / 128, BATCH / 128), 256>>>(b1p, cW2, cb2, b2p, BATCH, CC, CC);
    sgemm_kernel<false><<<dim3(NN / 128, BATCH / 128), 256>>>(b2p, cW3, cb3, coarse, BATCH, NN, CC);

    // 5. top-4
    top4_kernel<<<BATCH / 8, 256>>>(coarse, idxp);

    // 6. fine input assembly
    build_fine_kernel<<<ROWS_FINE, 256>>>(emb, ge, be);

    // 7-9. fine MLP
    sgemm_kernel<true><<<dim3(CC / 128, ROWS_FINE / 128), 256>>>(fine_in, fW1, fb1, b1p, ROWS_FINE, CC, 2 * CC);
    sgemm_kernel<true><<<dim3(CC / 128, ROWS_FINE / 128), 256>>>(b1p, fW2, fb2, b2p, ROWS_FINE, CC, CC);
    sgemm_kernel<false><<<dim3(FF / 128, ROWS_FINE / 128), 256>>>(b2p, fW3, fb3, fine, ROWS_FINE, FF, CC);

    // 10. logsumexp
    lse_kernel<<<ROWS_FINE, 256>>>();

    // 11. scatter + permute + write
    output_kernel<<<BATCH * 16, 256>>>(out);
}

// round 2
// speedup vs baseline: 2.1309x; 2.1309x over previous
#include <cuda_runtime.h>
#include <cstdint>
#include <math.h>

#define CC 768
#define NN 256
#define FF 512
#define BATCH 1024
#define ROWS_FINE 4096          // BATCH * 4
#define OUTROW 131073           // 1 + N*F
#define LOGF 6.238324625039508f // log(512)

// ---------------- scratch (no allocations allowed) ----------------
__device__ float g_xn[BATCH * CC];
__device__ float g_buf1[ROWS_FINE * CC];
__device__ float g_buf2[ROWS_FINE * CC];
__device__ float g_coarse[BATCH * NN];
__device__ int   g_idx[BATCH * 4];
__device__ float g_fine_in[ROWS_FINE * 2 * CC];
__device__ float g_fine[ROWS_FINE * FF];
__device__ float g_lse[ROWS_FINE];

__device__ __forceinline__ float gelu_tanh(float x) {
    float x3 = x * x * x;
    return 0.5f * x * (1.0f + tanhf(0.7978845608028654f * (x + 0.044715f * x3)));
}

__device__ __forceinline__ float tf32_rna(float x) {
    float r;
    asm("cvt.rna.tf32.f32 %0, %1;" : "=f"(r) : "f"(x));
    return r;
}

__device__ __forceinline__ void mma8(float* c, const uint32_t* a, const uint32_t* b) {
    asm volatile(
        "mma.sync.aligned.m16n8k8.row.col.f32.tf32.tf32.f32 "
        "{%0,%1,%2,%3}, {%4,%5,%6,%7}, {%8,%9}, {%0,%1,%2,%3};"
        : "+f"(c[0]), "+f"(c[1]), "+f"(c[2]), "+f"(c[3])
        : "r"(a[0]), "r"(a[1]), "r"(a[2]), "r"(a[3]), "r"(b[0]), "r"(b[1]));
}

// ---------------- tf32 tensor-core GEMM ----------------
// C[M,N] = act(A[M,K] @ W[K,N] + bias); row-major everywhere.
// BM=128, BK=16, BN in {64,128}. 256 threads = 8 warps (4 M x 2 N).
// SPLIT: 2-term tf32 decomposition (hi+lo) for ~fp32 accuracy (coarse head).
template <int BN, bool GELU, bool SPLIT>
__global__ void __launch_bounds__(256)
tcgemm(const float* __restrict__ A, const float* __restrict__ W,
       const float* __restrict__ bias, float* __restrict__ C,
       int M, int N, int K) {
    constexpr int BM = 128, BK = 16;
    constexpr int ASTR = BK + 4;      // 20 words: conflict-free frag loads
    constexpr int BSTR = BN + 8;      // 72 or 136: conflict-free frag loads
    constexpr int NSEG = SPLIT ? 2 : 1;
    constexpr int NBUF = SPLIT ? 1 : 2;   // split fits 48KB static only single-buffered
    constexpr int AS_SZ = BM * ASTR;
    constexpr int BS_SZ = BK * BSTR;
    constexpr int WN = BN / 2;        // warp n-extent
    constexpr int NT = WN / 8;        // n8 tiles per warp
    constexpr int NB = (BN == 128) ? 2 : 1;  // B float4 loads per thread

    __shared__ float As[NBUF][NSEG * AS_SZ];
    __shared__ float Bs[NBUF][NSEG * BS_SZ];

    const int tid = threadIdx.x;
    const int warp = tid >> 5, lane = tid & 31;
    const int wm = warp >> 1, wn = warp & 1;
    const int m0 = blockIdx.y * BM;
    const int n0 = blockIdx.x * BN;

    // loader coordinates
    const int ar = tid >> 2;            // 0..63 (rows ar, ar+64)
    const int ak = (tid & 3) << 2;      // 0,4,8,12
    int bkr, bn4;
    if (BN == 128) { bkr = tid >> 5; bn4 = (tid & 31) << 2; }   // rows bkr, bkr+8
    else           { bkr = tid >> 4; bn4 = (tid & 15) << 2; }   // row bkr

    const float* Ag = A + (size_t)(m0 + ar) * K + ak;
    const float* Bg = W + (size_t)bkr * N + n0 + bn4;

    float acc[2][NT][4];
#pragma unroll
    for (int mi = 0; mi < 2; mi++)
#pragma unroll
        for (int ni = 0; ni < NT; ni++)
#pragma unroll
            for (int r = 0; r < 4; r++) acc[mi][ni][r] = 0.f;

    float4 ra[2], rb[NB];
    const int nk = K / BK;

#define LOAD_TILE(K0)                                                          \
    {                                                                          \
        ra[0] = *(const float4*)(Ag + (K0));                                   \
        ra[1] = *(const float4*)(Ag + (size_t)64 * K + (K0));                  \
        rb[0] = *(const float4*)(Bg + (size_t)(K0) * N);                       \
        if (NB == 2) rb[1] = *(const float4*)(Bg + (size_t)((K0) + 8) * N);    \
    }

#define STORE_TILE(BUF)                                                        \
    {                                                                          \
        _Pragma("unroll")                                                      \
        for (int h = 0; h < 2; h++) {                                          \
            float* dst = &As[BUF][(ar + h * 64) * ASTR + ak];                  \
            float4 v = ra[h];                                                  \
            float4 hi;                                                         \
            hi.x = tf32_rna(v.x); hi.y = tf32_rna(v.y);                        \
            hi.z = tf32_rna(v.z); hi.w = tf32_rna(v.w);                        \
            *(float4*)dst = hi;                                                \
            if (SPLIT) {                                                       \
                float4 lo;                                                     \
                lo.x = tf32_rna(v.x - hi.x); lo.y = tf32_rna(v.y - hi.y);      \
                lo.z = tf32_rna(v.z - hi.z); lo.w = tf32_rna(v.w - hi.w);      \
                *(float4*)(dst + AS_SZ) = lo;                                  \
            }                                                                  \
        }                                                                      \
        _Pragma("unroll")                                                      \
        for (int h = 0; h < NB; h++) {                                         \
            float* dst = &Bs[BUF][(bkr + h * 8) * BSTR + bn4];                 \
            float4 v = rb[h];                                                  \
            float4 hi;                                                         \
            hi.x = tf32_rna(v.x); hi.y = tf32_rna(v.y);                        \
            hi.z = tf32_rna(v.z); hi.w = tf32_rna(v.w);                        \
            *(float4*)dst = hi;                                                \
            if (SPLIT) {                                                       \
                float4 lo;                                                     \
                lo.x = tf32_rna(v.x - hi.x); lo.y = tf32_rna(v.y - hi.y);      \
                lo.z = tf32_rna(v.z - hi.z); lo.w = tf32_rna(v.w - hi.w);      \
                *(float4*)(dst + BS_SZ) = lo;                                  \
            }                                                                  \
        }                                                                      \
    }

#define COMPUTE(BUF)                                                           \
    {                                                                          \
        _Pragma("unroll")                                                      \
        for (int ks = 0; ks < 2; ks++) {                                       \
            const int kk = ks * 8;                                             \
            uint32_t af[NSEG][2][4];                                           \
            _Pragma("unroll")                                                  \
            for (int mi = 0; mi < 2; mi++) {                                   \
                int mr = wm * 32 + mi * 16 + (lane >> 2);                      \
                _Pragma("unroll")                                              \
                for (int s = 0; s < NSEG; s++) {                               \
                    const float* base = &As[BUF][s * AS_SZ];                   \
                    af[s][mi][0] = __float_as_uint(base[mr * ASTR + kk + (lane & 3)]);         \
                    af[s][mi][1] = __float_as_uint(base[(mr + 8) * ASTR + kk + (lane & 3)]);   \
                    af[s][mi][2] = __float_as_uint(base[mr * ASTR + kk + 4 + (lane & 3)]);     \
                    af[s][mi][3] = __float_as_uint(base[(mr + 8) * ASTR + kk + 4 + (lane & 3)]);\
                }                                                              \
            }                                                                  \
            uint32_t bf[NSEG][NT][2];                                          \
            _Pragma("unroll")                                                  \
            for (int ni = 0; ni < NT; ni++) {                                  \
                int nc = wn * WN + ni * 8 + (lane >> 2);                       \
                _Pragma("unroll")                                              \
                for (int s = 0; s < NSEG; s++) {                               \
                    const float* base = &Bs[BUF][s * BS_SZ];                   \
                    bf[s][ni][0] = __float_as_uint(base[(kk + (lane & 3)) * BSTR + nc]);       \
                    bf[s][ni][1] = __float_as_uint(base[(kk + 4 + (lane & 3)) * BSTR + nc]);   \
                }                                                              \
            }                                                                  \
            _Pragma("unroll")                                                  \
            for (int mi = 0; mi < 2; mi++)                                     \
                _Pragma("unroll")                                              \
                for (int ni = 0; ni < NT; ni++) {                              \
                    mma8(acc[mi][ni], af[0][mi], bf[0][ni]);                   \
                    if (SPLIT) {                                               \
                        mma8(acc[mi][ni], af[0][mi], bf[1][ni]);               \
                        mma8(acc[mi][ni], af[1][mi], bf[0][ni]);               \
                    }                                                          \
                }                                                              \
        }                                                                      \
    }

    if (!SPLIT) {
        // double-buffered pipeline
        LOAD_TILE(0);
        STORE_TILE(0);
        __syncthreads();
        int buf = 0;
        for (int it = 0; it < nk; it++) {
            if (it + 1 < nk) LOAD_TILE((it + 1) * BK);
            COMPUTE(buf);
            if (it + 1 < nk) STORE_TILE(buf ^ 1);
            __syncthreads();
            buf ^= 1;
        }
    } else {
        // single-buffered (smem budget), gmem prefetch in regs
        LOAD_TILE(0);
        for (int it = 0; it < nk; it++) {
            STORE_TILE(0);
            __syncthreads();
            if (it + 1 < nk) LOAD_TILE((it + 1) * BK);
            COMPUTE(0);
            __syncthreads();
        }
    }

    // epilogue
#pragma unroll
    for (int mi = 0; mi < 2; mi++) {
        int gr = m0 + wm * 32 + mi * 16 + (lane >> 2);
#pragma unroll
        for (int ni = 0; ni < NT; ni++) {
            int gc = n0 + wn * WN + ni * 8 + ((lane & 3) << 1);
            float b0v = bias[gc], b1v = bias[gc + 1];
            float v0 = acc[mi][ni][0] + b0v;
            float v1 = acc[mi][ni][1] + b1v;
            float v2 = acc[mi][ni][2] + b0v;
            float v3 = acc[mi][ni][3] + b1v;
            if (GELU) {
                v0 = gelu_tanh(v0); v1 = gelu_tanh(v1);
                v2 = gelu_tanh(v2); v3 = gelu_tanh(v3);
            }
            float2 p0 = {v0, v1}, p1 = {v2, v3};
            *(float2*)&C[(size_t)gr * N + gc] = p0;
            *(float2*)&C[(size_t)(gr + 8) * N + gc] = p1;
        }
    }
#undef LOAD_TILE
#undef STORE_TILE
#undef COMPUTE
}

// ---------------- LayerNorm(x) + no_op head ----------------
__global__ void ln_noop_kernel(const float* __restrict__ x,
                               const float* __restrict__ gin,
                               const float* __restrict__ bin,
                               const float* __restrict__ nW,
                               const float* __restrict__ nb,
                               float* __restrict__ out) {
    int b = blockIdx.x, tid = threadIdx.x;
    const float* xr = x + (size_t)b * CC;
    __shared__ float red[256];
    float v[3];
    float s = 0.f, ss = 0.f;
#pragma unroll
    for (int i = 0; i < 3; i++) {
        v[i] = xr[tid + i * 256];
        s += v[i];
        ss += v[i] * v[i];
    }
    red[tid] = s; __syncthreads();
    for (int o = 128; o > 0; o >>= 1) { if (tid < o) red[tid] += red[tid + o]; __syncthreads(); }
    float mean = red[0] * (1.0f / CC);
    __syncthreads();
    red[tid] = ss; __syncthreads();
    for (int o = 128; o > 0; o >>= 1) { if (tid < o) red[tid] += red[tid + o]; __syncthreads(); }
    float var = red[0] * (1.0f / CC) - mean * mean;
    float rstd = rsqrtf(var + 1e-5f);
    __syncthreads();
    float dot = 0.f;
#pragma unroll
    for (int i = 0; i < 3; i++) {
        int c = tid + i * 256;
        float xn = (v[i] - mean) * rstd * gin[c] + bin[c];
        g_xn[(size_t)b * CC + c] = xn;
        dot += xn * nW[c];
    }
    red[tid] = dot; __syncthreads();
    for (int o = 128; o > 0; o >>= 1) { if (tid < o) red[tid] += red[tid + o]; __syncthreads(); }
    if (tid == 0) out[(size_t)b * OUTROW] = red[0] + nb[0];
}

// ---------------- top-4 of coarse row, one warp per row ----------------
__global__ void top4_kernel(const float* __restrict__ coarse, int* __restrict__ idx) {
    int warp = threadIdx.x >> 5, lane = threadIdx.x & 31;
    int row = blockIdx.x * 8 + warp;
    const float* cr = coarse + (size_t)row * NN;
    float v[8];
    int id[8];
#pragma unroll
    for (int i = 0; i < 8; i++) {
        id[i] = lane + i * 32;
        v[i] = cr[id[i]];
    }
#pragma unroll
    for (int r = 0; r < 4; r++) {
        float bv = -INFINITY;
        int bi = 1 << 30;
#pragma unroll
        for (int i = 0; i < 8; i++)
            if (v[i] > bv || (v[i] == bv && id[i] < bi)) { bv = v[i]; bi = id[i]; }
        for (int o = 16; o > 0; o >>= 1) {
            float ov = __shfl_xor_sync(0xffffffffu, bv, o);
            int oi = __shfl_xor_sync(0xffffffffu, bi, o);
            if (ov > bv || (ov == bv && oi < bi)) { bv = ov; bi = oi; }
        }
        if (lane == 0) idx[row * 4 + r] = bi;
#pragma unroll
        for (int i = 0; i < 8; i++)
            if (id[i] == bi) v[i] = -INFINITY;
    }
}

// ---------------- fine_in = concat(xn, LN(emb[idx])) ----------------
__global__ void build_fine_kernel(const float* __restrict__ emb,
                                  const float* __restrict__ ge,
                                  const float* __restrict__ be) {
    int r = blockIdx.x, tid = threadIdx.x;
    int b = r >> 2;
    int n = g_idx[r];
    const float* er = emb + (size_t)n * CC;
    __shared__ float red[256];
    float v[3];
    float s = 0.f, ss = 0.f;
#pragma unroll
    for (int i = 0; i < 3; i++) {
        v[i] = er[tid + i * 256];
        s += v[i];
        ss += v[i] * v[i];
    }
    red[tid] = s; __syncthreads();
    for (int o = 128; o > 0; o >>= 1) { if (tid < o) red[tid] += red[tid + o]; __syncthreads(); }
    float mean = red[0] * (1.0f / CC);
    __syncthreads();
    red[tid] = ss; __syncthreads();
    for (int o = 128; o > 0; o >>= 1) { if (tid < o) red[tid] += red[tid + o]; __syncthreads(); }
    float var = red[0] * (1.0f / CC) - mean * mean;
    float rstd = rsqrtf(var + 1e-5f);
    float* fo = g_fine_in + (size_t)r * (2 * CC);
#pragma unroll
    for (int i = 0; i < 3; i++) {
        int c = tid + i * 256;
        fo[c] = g_xn[(size_t)b * CC + c];
        fo[CC + c] = (v[i] - mean) * rstd * ge[c] + be[c];
    }
}

// ---------------- logsumexp over fine rows ----------------
__global__ void lse_kernel() {
    int r = blockIdx.x, tid = threadIdx.x;
    const float* fr = g_fine + (size_t)r * FF;
    __shared__ float red[256];
    float a = fr[tid], b2 = fr[tid + 256];
    red[tid] = fmaxf(a, b2); __syncthreads();
    for (int o = 128; o > 0; o >>= 1) { if (tid < o) red[tid] = fmaxf(red[tid], red[tid + o]); __syncthreads(); }
    float m = red[0];
    __syncthreads();
    red[tid] = expf(a - m) + expf(b2 - m); __syncthreads();
    for (int o = 128; o > 0; o >>= 1) { if (tid < o) red[tid] += red[tid + o]; __syncthreads(); }
    if (tid == 0) g_lse[r] = m + logf(red[0]);
}

// ---------------- scatter + permute + final write (537 MB) ----------------
__global__ void output_kernel(float* __restrict__ out) {
    int b = blockIdx.x >> 4;
    int chunk = blockIdx.x & 15;
    int tid = threadIdx.x;
    __shared__ float sc[NN];
    __shared__ int sidx[4];
    __shared__ float slse[4];
    sc[tid] = g_coarse[(size_t)b * NN + tid];
    if (tid < 4) {
        sidx[tid] = g_idx[b * 4 + tid];
        slse[tid] = g_lse[b * 4 + tid];
    }
    __syncthreads();
    size_t obase = (size_t)b * OUTROW + 1;
#pragma unroll 4
    for (int it = 0; it < 32; it++) {
        int o = chunk * 8192 + it * 256 + tid;
        int ch = o >> 13, fh = (o >> 9) & 15, cw = (o >> 5) & 15, j = o & 31;
        int n = (ch << 4) + cw;
        int f = (fh << 5) + j;
        float v = sc[n] - LOGF;
#pragma unroll
        for (int k = 0; k < 4; k++)
            if (sidx[k] == n)
                v = sc[n] + g_fine[(size_t)(b * 4 + k) * FF + f] - slse[k];
        out[obase + o] = v;
    }
}

// ---------------- launch ----------------
extern "C" void kernel_launch(void* const* d_in, const int* in_sizes, int n_in,
                              void* d_out, int out_size) {
    (void)in_sizes; (void)n_in; (void)out_size;
    const float* x    = (const float*)d_in[0];
    const float* gin  = (const float*)d_in[1];
    const float* bin  = (const float*)d_in[2];
    const float* cW1  = (const float*)d_in[3];
    const float* cb1  = (const float*)d_in[4];
    const float* cW2  = (const float*)d_in[5];
    const float* cb2  = (const float*)d_in[6];
    const float* cW3  = (const float*)d_in[7];
    const float* cb3  = (const float*)d_in[8];
    const float* emb  = (const float*)d_in[9];
    const float* ge   = (const float*)d_in[10];
    const float* be   = (const float*)d_in[11];
    const float* fW1  = (const float*)d_in[12];
    const float* fb1  = (const float*)d_in[13];
    const float* fW2  = (const float*)d_in[14];
    const float* fb2  = (const float*)d_in[15];
    const float* fW3  = (const float*)d_in[16];
    const float* fb3  = (const float*)d_in[17];
    const float* nW   = (const float*)d_in[18];
    const float* nb   = (const float*)d_in[19];
    float* out = (float*)d_out;

    float *xn, *b1p, *b2p, *coarse, *fine_in, *fine;
    int* idxp;
    cudaGetSymbolAddress((void**)&xn, g_xn);
    cudaGetSymbolAddress((void**)&b1p, g_buf1);
    cudaGetSymbolAddress((void**)&b2p, g_buf2);
    cudaGetSymbolAddress((void**)&coarse, g_coarse);
    cudaGetSymbolAddress((void**)&idxp, g_idx);
    cudaGetSymbolAddress((void**)&fine_in, g_fine_in);
    cudaGetSymbolAddress((void**)&fine, g_fine);

    // 1. LN + no_op
    ln_noop_kernel<<<BATCH, 256>>>(x, gin, bin, nW, nb, out);

    // 2-4. coarse MLP (tf32 split: ~fp32 accuracy -> exact top-k)
    tcgemm<64, true,  true><<<dim3(CC / 64, BATCH / 128), 256>>>(xn,  cW1, cb1, b1p,    BATCH, CC, CC);
    tcgemm<64, true,  true><<<dim3(CC / 64, BATCH / 128), 256>>>(b1p, cW2, cb2, b2p,    BATCH, CC, CC);
    tcgemm<64, false, true><<<dim3(NN / 64, BATCH / 128), 256>>>(b2p, cW3, cb3, coarse, BATCH, NN, CC);

    // 5. top-4
    top4_kernel<<<BATCH / 8, 256>>>(coarse, idxp);

    // 6. fine input assembly
    build_fine_kernel<<<ROWS_FINE, 256>>>(emb, ge, be);

    // 7-9. fine MLP (single-pass tf32)
    tcgemm<128, true,  false><<<dim3(CC / 128, ROWS_FINE / 128), 256>>>(fine_in, fW1, fb1, b1p,  ROWS_FINE, CC, 2 * CC);
    tcgemm<128, true,  false><<<dim3(CC / 128, ROWS_FINE / 128), 256>>>(b1p,     fW2, fb2, b2p,  ROWS_FINE, CC, CC);
    tcgemm<128, false, false><<<dim3(FF / 128, ROWS_FINE / 128), 256>>>(b2p,     fW3, fb3, fine, ROWS_FINE, FF, CC);

    // 10. logsumexp
    lse_kernel<<<ROWS_FINE, 256>>>();

    // 11. scatter + permute + write
    output_kernel<<<BATCH * 16, 256>>>(out);
}

// round 3
// speedup vs baseline: 2.3688x; 1.1116x over previous
#include <cuda_runtime.h>
#include <cstdint>
#include <math.h>

#define CC 768
#define NN 256
#define FF 512
#define BATCH 1024
#define ROWS_FINE 4096          // BATCH * 4
#define OUTROW 131073           // 1 + N*F
#define LOGF 6.238324625039508f // log(512)

// ---------------- scratch (no allocations allowed) ----------------
__device__ float g_xn[BATCH * CC];
__device__ float g_xnlo[BATCH * CC];
__device__ float g_buf1[ROWS_FINE * CC];
__device__ float g_buf1lo[BATCH * CC];
__device__ float g_buf2[ROWS_FINE * CC];
__device__ float g_buf2lo[BATCH * CC];
__device__ float g_coarse[BATCH * NN];
__device__ int   g_idx[BATCH * 4];
__device__ float g_fine_in[ROWS_FINE * 2 * CC];
__device__ float g_fine[ROWS_FINE * FF];
__device__ float g_lse[ROWS_FINE];
// pre-rounded weights
__device__ float g_cW1hi[CC * CC], g_cW1lo[CC * CC];
__device__ float g_cW2hi[CC * CC], g_cW2lo[CC * CC];
__device__ float g_cW3hi[CC * NN], g_cW3lo[CC * NN];
__device__ float g_fW1r[2 * CC * CC];
__device__ float g_fW2r[CC * CC];
__device__ float g_fW3r[CC * FF];

__device__ __forceinline__ float gelu_tanh(float x) {
    float x3 = x * x * x;
    return 0.5f * x * (1.0f + tanhf(0.7978845608028654f * (x + 0.044715f * x3)));
}

__device__ __forceinline__ float tf32_rna(float x) {
    float r;
    asm("cvt.rna.tf32.f32 %0, %1;" : "=f"(r) : "f"(x));
    return r;
}

__device__ __forceinline__ void mma8(float* c, const uint32_t* a, const uint32_t* b) {
    asm volatile(
        "mma.sync.aligned.m16n8k8.row.col.f32.tf32.tf32.f32 "
        "{%0,%1,%2,%3}, {%4,%5,%6,%7}, {%8,%9}, {%0,%1,%2,%3};"
        : "+f"(c[0]), "+f"(c[1]), "+f"(c[2]), "+f"(c[3])
        : "r"(a[0]), "r"(a[1]), "r"(a[2]), "r"(a[3]), "r"(b[0]), "r"(b[1]));
}

__device__ __forceinline__ void cp16(void* s, const void* g) {
    uint32_t sa = (uint32_t)__cvta_generic_to_shared(s);
    asm volatile("cp.async.cg.shared.global [%0], [%1], 16;" :: "r"(sa), "l"(g));
}

// ---------------- weight pre-rounding (once per launch, ~16MB) ----------------
__global__ void round_weights(const float* __restrict__ cW1, const float* __restrict__ cW2,
                              const float* __restrict__ cW3, const float* __restrict__ fW1,
                              const float* __restrict__ fW2, const float* __restrict__ fW3) {
    int stride = gridDim.x * blockDim.x;
    int i0 = blockIdx.x * blockDim.x + threadIdx.x;
    for (int i = i0; i < CC * CC; i += stride) {
        float v = cW1[i], h = tf32_rna(v);
        g_cW1hi[i] = h; g_cW1lo[i] = tf32_rna(v - h);
        v = cW2[i]; h = tf32_rna(v);
        g_cW2hi[i] = h; g_cW2lo[i] = tf32_rna(v - h);
        g_fW2r[i] = tf32_rna(fW2[i]);
    }
    for (int i = i0; i < CC * NN; i += stride) {
        float v = cW3[i], h = tf32_rna(v);
        g_cW3hi[i] = h; g_cW3lo[i] = tf32_rna(v - h);
    }
    for (int i = i0; i < 2 * CC * CC; i += stride) g_fW1r[i] = tf32_rna(fW1[i]);
    for (int i = i0; i < CC * FF; i += stride) g_fW3r[i] = tf32_rna(fW3[i]);
}

// ---------------- tf32 tensor-core GEMM, cp.async 4-stage pipeline ----------------
// Operands are PRE-ROUNDED to tf32 (hardware truncation is then exact).
// SPLIT_IN: A = Ahi+Alo, W = Whi+Wlo, 3 MMAs -> ~fp32 accuracy.
// SPLIT_OUT: write hi/lo rounded pair. ROUND_OUT: write rna-rounded value.
template <int BM, int BN, bool GELU, bool SPLIT_IN, bool SPLIT_OUT, bool ROUND_OUT>
__global__ void __launch_bounds__(256, 2)
tcgemm(const float* __restrict__ Ahi, const float* __restrict__ Alo,
       const float* __restrict__ Whi, const float* __restrict__ Wlo,
       const float* __restrict__ bias, float* __restrict__ C, float* __restrict__ Clo,
       int M, int N, int K) {
    constexpr int BK = 16, STAGES = 4;
    constexpr int ASTR = BK + 4;
    constexpr int BSTR = BN + 8;
    constexpr int NSEG = SPLIT_IN ? 2 : 1;
    constexpr int A_ST = BM * ASTR;
    constexpr int B_ST = BK * BSTR;
    constexpr int STW = NSEG * (A_ST + B_ST);   // words per stage
    constexpr int WN_CNT = (BM == 128) ? 2 : 4; // warp grid: (BM/32) x WN_CNT
    constexpr int WN = BN / WN_CNT;
    constexpr int NT = WN / 8;
    constexpr int AH = BM / 64;                 // A 16B-chunks per thread
    constexpr int BH = BN / 64;                 // B 16B-chunks per thread

    extern __shared__ float smem[];
    const int tid = threadIdx.x;
    const int warp = tid >> 5, lane = tid & 31;
    const int wm = warp / WN_CNT, wn = warp % WN_CNT;
    const int lr = lane >> 2, lc = lane & 3;
    const int m0 = blockIdx.y * BM, n0 = blockIdx.x * BN;

    float acc[2][NT][4];
#pragma unroll
    for (int mi = 0; mi < 2; mi++)
#pragma unroll
        for (int ni = 0; ni < NT; ni++)
#pragma unroll
            for (int r = 0; r < 4; r++) acc[mi][ni][r] = 0.f;

    const int nk = K / BK;

    auto load_tile = [&](int stg, int k0) {
        float* sA = smem + stg * STW;
        float* sB = sA + NSEG * A_ST;
#pragma unroll
        for (int h = 0; h < AH; h++) {
            int c = tid + h * 256;
            int row = c >> 2, kc = (c & 3) << 2;
            size_t goff = (size_t)(m0 + row) * K + k0 + kc;
            cp16(sA + row * ASTR + kc, Ahi + goff);
            if (SPLIT_IN) cp16(sA + A_ST + row * ASTR + kc, Alo + goff);
        }
#pragma unroll
        for (int h = 0; h < BH; h++) {
            int c = tid + h * 256;
            int row = c / (BN / 4), col = (c % (BN / 4)) << 2;
            size_t goff = (size_t)(k0 + row) * N + n0 + col;
            cp16(sB + row * BSTR + col, Whi + goff);
            if (SPLIT_IN) cp16(sB + B_ST + row * BSTR + col, Wlo + goff);
        }
    };

    for (int s = 0; s < STAGES - 1; s++) {
        load_tile(s, s * BK);
        asm volatile("cp.async.commit_group;");
    }

    for (int it = 0; it < nk; it++) {
        asm volatile("cp.async.wait_group %0;" :: "n"(STAGES - 2));
        __syncthreads();
        int pre = it + STAGES - 1;
        if (pre < nk) load_tile(pre % STAGES, pre * BK);
        asm volatile("cp.async.commit_group;");

        const float* sA = smem + (it % STAGES) * STW;
        const float* sB = sA + NSEG * A_ST;
#pragma unroll
        for (int ks = 0; ks < 2; ks++) {
            const int kk = ks * 8;
            uint32_t af[NSEG][2][4];
#pragma unroll
            for (int mi = 0; mi < 2; mi++) {
                int mr = wm * 32 + mi * 16 + lr;
#pragma unroll
                for (int s = 0; s < NSEG; s++) {
                    const float* base = sA + s * A_ST;
                    af[s][mi][0] = __float_as_uint(base[mr * ASTR + kk + lc]);
                    af[s][mi][1] = __float_as_uint(base[(mr + 8) * ASTR + kk + lc]);
                    af[s][mi][2] = __float_as_uint(base[mr * ASTR + kk + 4 + lc]);
                    af[s][mi][3] = __float_as_uint(base[(mr + 8) * ASTR + kk + 4 + lc]);
                }
            }
            uint32_t bf[NSEG][NT][2];
#pragma unroll
            for (int ni = 0; ni < NT; ni++) {
                int nc = wn * WN + ni * 8 + lr;
#pragma unroll
                for (int s = 0; s < NSEG; s++) {
                    const float* base = sB + s * B_ST;
                    bf[s][ni][0] = __float_as_uint(base[(kk + lc) * BSTR + nc]);
                    bf[s][ni][1] = __float_as_uint(base[(kk + 4 + lc) * BSTR + nc]);
                }
            }
#pragma unroll
            for (int mi = 0; mi < 2; mi++)
#pragma unroll
                for (int ni = 0; ni < NT; ni++) {
                    mma8(acc[mi][ni], af[0][mi], bf[0][ni]);
                    if (SPLIT_IN) {
                        mma8(acc[mi][ni], af[0][mi], bf[1][ni]);
                        mma8(acc[mi][ni], af[1][mi], bf[0][ni]);
                    }
                }
        }
    }
    asm volatile("cp.async.wait_group 0;");

    // epilogue
#pragma unroll
    for (int mi = 0; mi < 2; mi++) {
        int gr = m0 + wm * 32 + mi * 16 + lr;
#pragma unroll
        for (int ni = 0; ni < NT; ni++) {
            int gc = n0 + wn * WN + ni * 8 + (lc << 1);
            float b0v = bias[gc], b1v = bias[gc + 1];
#pragma unroll
            for (int half = 0; half < 2; half++) {
                size_t row = (size_t)(gr + half * 8) * N + gc;
                float v0 = acc[mi][ni][half * 2 + 0] + b0v;
                float v1 = acc[mi][ni][half * 2 + 1] + b1v;
                if (GELU) { v0 = gelu_tanh(v0); v1 = gelu_tanh(v1); }
                if (SPLIT_OUT) {
                    float h0 = tf32_rna(v0), h1 = tf32_rna(v1);
                    float2 hi = {h0, h1};
                    float2 lo = {tf32_rna(v0 - h0), tf32_rna(v1 - h1)};
                    *(float2*)&C[row] = hi;
                    *(float2*)&Clo[row] = lo;
                } else if (ROUND_OUT) {
                    float2 p = {tf32_rna(v0), tf32_rna(v1)};
                    *(float2*)&C[row] = p;
                } else {
                    float2 p = {v0, v1};
                    *(float2*)&C[row] = p;
                }
            }
        }
    }
}

// ---------------- LayerNorm(x) + no_op head (writes tf32 hi/lo) ----------------
__global__ void ln_noop_kernel(const float* __restrict__ x,
                               const float* __restrict__ gin,
                               const float* __restrict__ bin,
                               const float* __restrict__ nW,
                               const float* __restrict__ nb,
                               float* __restrict__ out) {
    int b = blockIdx.x, tid = threadIdx.x;
    const float* xr = x + (size_t)b * CC;
    __shared__ float red[256];
    float v[3];
    float s = 0.f, ss = 0.f;
#pragma unroll
    for (int i = 0; i < 3; i++) {
        v[i] = xr[tid + i * 256];
        s += v[i];
        ss += v[i] * v[i];
    }
    red[tid] = s; __syncthreads();
    for (int o = 128; o > 0; o >>= 1) { if (tid < o) red[tid] += red[tid + o]; __syncthreads(); }
    float mean = red[0] * (1.0f / CC);
    __syncthreads();
    red[tid] = ss; __syncthreads();
    for (int o = 128; o > 0; o >>= 1) { if (tid < o) red[tid] += red[tid + o]; __syncthreads(); }
    float var = red[0] * (1.0f / CC) - mean * mean;
    float rstd = rsqrtf(var + 1e-5f);
    __syncthreads();
    float dot = 0.f;
#pragma unroll
    for (int i = 0; i < 3; i++) {
        int c = tid + i * 256;
        float xn = (v[i] - mean) * rstd * gin[c] + bin[c];
        float h = tf32_rna(xn);
        g_xn[(size_t)b * CC + c] = h;
        g_xnlo[(size_t)b * CC + c] = tf32_rna(xn - h);
        dot += xn * nW[c];
    }
    red[tid] = dot; __syncthreads();
    for (int o = 128; o > 0; o >>= 1) { if (tid < o) red[tid] += red[tid + o]; __syncthreads(); }
    if (tid == 0) out[(size_t)b * OUTROW] = red[0] + nb[0];
}

// ---------------- top-4 of coarse row, one warp per row ----------------
__global__ void top4_kernel(const float* __restrict__ coarse, int* __restrict__ idx) {
    int warp = threadIdx.x >> 5, lane = threadIdx.x & 31;
    int row = blockIdx.x * 8 + warp;
    const float* cr = coarse + (size_t)row * NN;
    float v[8];
    int id[8];
#pragma unroll
    for (int i = 0; i < 8; i++) {
        id[i] = lane + i * 32;
        v[i] = cr[id[i]];
    }
#pragma unroll
    for (int r = 0; r < 4; r++) {
        float bv = -INFINITY;
        int bi = 1 << 30;
#pragma unroll
        for (int i = 0; i < 8; i++)
            if (v[i] > bv || (v[i] == bv && id[i] < bi)) { bv = v[i]; bi = id[i]; }
        for (int o = 16; o > 0; o >>= 1) {
            float ov = __shfl_xor_sync(0xffffffffu, bv, o);
            int oi = __shfl_xor_sync(0xffffffffu, bi, o);
            if (ov > bv || (ov == bv && oi < bi)) { bv = ov; bi = oi; }
        }
        if (lane == 0) idx[row * 4 + r] = bi;
#pragma unroll
        for (int i = 0; i < 8; i++)
            if (id[i] == bi) v[i] = -INFINITY;
    }
}

// ---------------- fine_in = concat(xn, LN(emb[idx])) (tf32-rounded) ----------------
__global__ void build_fine_kernel(const float* __restrict__ emb,
                                  const float* __restrict__ ge,
                                  const float* __restrict__ be) {
    int r = blockIdx.x, tid = threadIdx.x;
    int b = r >> 2;
    int n = g_idx[r];
    const float* er = emb + (size_t)n * CC;
    __shared__ float red[256];
    float v[3];
    float s = 0.f, ss = 0.f;
#pragma unroll
    for (int i = 0; i < 3; i++) {
        v[i] = er[tid + i * 256];
        s += v[i];
        ss += v[i] * v[i];
    }
    red[tid] = s; __syncthreads();
    for (int o = 128; o > 0; o >>= 1) { if (tid < o) red[tid] += red[tid + o]; __syncthreads(); }
    float mean = red[0] * (1.0f / CC);
    __syncthreads();
    red[tid] = ss; __syncthreads();
    for (int o = 128; o > 0; o >>= 1) { if (tid < o) red[tid] += red[tid + o]; __syncthreads(); }
    float var = red[0] * (1.0f / CC) - mean * mean;
    float rstd = rsqrtf(var + 1e-5f);
    float* fo = g_fine_in + (size_t)r * (2 * CC);
#pragma unroll
    for (int i = 0; i < 3; i++) {
        int c = tid + i * 256;
        fo[c] = g_xn[(size_t)b * CC + c];  // already tf32-rounded
        fo[CC + c] = tf32_rna((v[i] - mean) * rstd * ge[c] + be[c]);
    }
}

// ---------------- logsumexp over fine rows ----------------
__global__ void lse_kernel() {
    int r = blockIdx.x, tid = threadIdx.x;
    const float* fr = g_fine + (size_t)r * FF;
    __shared__ float red[256];
    float a = fr[tid], b2 = fr[tid + 256];
    red[tid] = fmaxf(a, b2); __syncthreads();
    for (int o = 128; o > 0; o >>= 1) { if (tid < o) red[tid] = fmaxf(red[tid], red[tid + o]); __syncthreads(); }
    float m = red[0];
    __syncthreads();
    red[tid] = expf(a - m) + expf(b2 - m); __syncthreads();
    for (int o = 128; o > 0; o >>= 1) { if (tid < o) red[tid] += red[tid + o]; __syncthreads(); }
    if (tid == 0) g_lse[r] = m + logf(red[0]);
}

// ---------------- scatter + permute + final write (537 MB) ----------------
__global__ void output_kernel(float* __restrict__ out) {
    int b = blockIdx.x >> 4;
    int chunk = blockIdx.x & 15;
    int tid = threadIdx.x;
    __shared__ float sc[NN];
    __shared__ int sidx[4];
    __shared__ float slse[4];
    sc[tid] = g_coarse[(size_t)b * NN + tid];
    if (tid < 4) {
        sidx[tid] = g_idx[b * 4 + tid];
        slse[tid] = g_lse[b * 4 + tid];
    }
    __syncthreads();
    size_t obase = (size_t)b * OUTROW + 1;
#pragma unroll 4
    for (int it = 0; it < 32; it++) {
        int o = chunk * 8192 + it * 256 + tid;
        int ch = o >> 13, fh = (o >> 9) & 15, cw = (o >> 5) & 15, j = o & 31;
        int n = (ch << 4) + cw;
        int f = (fh << 5) + j;
        float v = sc[n] - LOGF;
#pragma unroll
        for (int k = 0; k < 4; k++)
            if (sidx[k] == n)
                v = sc[n] + g_fine[(size_t)(b * 4 + k) * FF + f] - slse[k];
        out[obase + o] = v;
    }
}

// ---------------- launch ----------------
extern "C" void kernel_launch(void* const* d_in, const int* in_sizes, int n_in,
                              void* d_out, int out_size) {
    (void)in_sizes; (void)n_in; (void)out_size;
    const float* x    = (const float*)d_in[0];
    const float* gin  = (const float*)d_in[1];
    const float* bin  = (const float*)d_in[2];
    const float* cW1  = (const float*)d_in[3];
    const float* cb1  = (const float*)d_in[4];
    const float* cW2  = (const float*)d_in[5];
    const float* cb2  = (const float*)d_in[6];
    const float* cW3  = (const float*)d_in[7];
    const float* cb3  = (const float*)d_in[8];
    const float* emb  = (const float*)d_in[9];
    const float* ge   = (const float*)d_in[10];
    const float* be   = (const float*)d_in[11];
    const float* fW1  = (const float*)d_in[12];
    const float* fb1  = (const float*)d_in[13];
    const float* fW2  = (const float*)d_in[14];
    const float* fb2  = (const float*)d_in[15];
    const float* fW3  = (const float*)d_in[16];
    const float* fb3  = (const float*)d_in[17];
    const float* nW   = (const float*)d_in[18];
    const float* nb   = (const float*)d_in[19];
    float* out = (float*)d_out;

    float *xn, *xnlo, *b1p, *b1lo, *b2p, *b2lo, *coarse, *fine_in, *fine;
    float *cw1h, *cw1l, *cw2h, *cw2l, *cw3h, *cw3l, *fw1r, *fw2r, *fw3r;
    int* idxp;
    cudaGetSymbolAddress((void**)&xn, g_xn);
    cudaGetSymbolAddress((void**)&xnlo, g_xnlo);
    cudaGetSymbolAddress((void**)&b1p, g_buf1);
    cudaGetSymbolAddress((void**)&b1lo, g_buf1lo);
    cudaGetSymbolAddress((void**)&b2p, g_buf2);
    cudaGetSymbolAddress((void**)&b2lo, g_buf2lo);
    cudaGetSymbolAddress((void**)&coarse, g_coarse);
    cudaGetSymbolAddress((void**)&idxp, g_idx);
    cudaGetSymbolAddress((void**)&fine_in, g_fine_in);
    cudaGetSymbolAddress((void**)&fine, g_fine);
    cudaGetSymbolAddress((void**)&cw1h, g_cW1hi);
    cudaGetSymbolAddress((void**)&cw1l, g_cW1lo);
    cudaGetSymbolAddress((void**)&cw2h, g_cW2hi);
    cudaGetSymbolAddress((void**)&cw2l, g_cW2lo);
    cudaGetSymbolAddress((void**)&cw3h, g_cW3hi);
    cudaGetSymbolAddress((void**)&cw3l, g_cW3lo);
    cudaGetSymbolAddress((void**)&fw1r, g_fW1r);
    cudaGetSymbolAddress((void**)&fw2r, g_fW2r);
    cudaGetSymbolAddress((void**)&fw3r, g_fW3r);

    // dynamic smem opt-in (4 stages)
    constexpr int SM_FINE   = 4 * (128 * 20 + 16 * 136) * 4;        // 75776
    constexpr int SM_COARSE = 4 * 2 * (64 * 20 + 16 * 72) * 4;      // 77824
    cudaFuncSetAttribute((void*)tcgemm<64, 64, true,  true,  true,  false>, cudaFuncAttributeMaxDynamicSharedMemorySize, SM_COARSE);
    cudaFuncSetAttribute((void*)tcgemm<64, 64, false, true,  false, false>, cudaFuncAttributeMaxDynamicSharedMemorySize, SM_COARSE);
    cudaFuncSetAttribute((void*)tcgemm<128, 128, true,  false, false, true>,  cudaFuncAttributeMaxDynamicSharedMemorySize, SM_FINE);
    cudaFuncSetAttribute((void*)tcgemm<128, 128, false, false, false, false>, cudaFuncAttributeMaxDynamicSharedMemorySize, SM_FINE);

    // 0. round weights to tf32 (hi/lo for coarse path)
    round_weights<<<592, 256>>>(cW1, cW2, cW3, fW1, fW2, fW3);

    // 1. LN + no_op
    ln_noop_kernel<<<BATCH, 256>>>(x, gin, bin, nW, nb, out);

    // 2-4. coarse MLP (split tf32, 64x64 tiles -> 192/192/64 blocks)
    tcgemm<64, 64, true,  true,  true,  false><<<dim3(CC / 64, BATCH / 64), 256, SM_COARSE>>>(
        xn, xnlo, cw1h, cw1l, cb1, b1p, b1lo, BATCH, CC, CC);
    tcgemm<64, 64, true,  true,  true,  false><<<dim3(CC / 64, BATCH / 64), 256, SM_COARSE>>>(
        b1p, b1lo, cw2h, cw2l, cb2, b2p, b2lo, BATCH, CC, CC);
    tcgemm<64, 64, false, true,  false, false><<<dim3(NN / 64, BATCH / 64), 256, SM_COARSE>>>(
        b2p, b2lo, cw3h, cw3l, cb3, coarse, nullptr, BATCH, NN, CC);

    // 5. top-4
    top4_kernel<<<BATCH / 8, 256>>>(coarse, idxp);

    // 6. fine input assembly
    build_fine_kernel<<<ROWS_FINE, 256>>>(emb, ge, be);

    // 7-9. fine MLP (single tf32, 128x128 tiles)
    tcgemm<128, 128, true,  false, false, true><<<dim3(CC / 128, ROWS_FINE / 128), 256, SM_FINE>>>(
        fine_in, nullptr, fw1r, nullptr, fb1, b1p, nullptr, ROWS_FINE, CC, 2 * CC);
    tcgemm<128, 128, true,  false, false, true><<<dim3(CC / 128, ROWS_FINE / 128), 256, SM_FINE>>>(
        b1p, nullptr, fw2r, nullptr, fb2, b2p, nullptr, ROWS_FINE, CC, CC);
    tcgemm<128, 128, false, false, false, false><<<dim3(FF / 128, ROWS_FINE / 128), 256, SM_FINE>>>(
        b2p, nullptr, fw3r, nullptr, fb3, fine, nullptr, ROWS_FINE, FF, CC);

    // 10. logsumexp
    lse_kernel<<<ROWS_FINE, 256>>>();

    // 11. scatter + permute + write
    output_kernel<<<BATCH * 16, 256>>>(out);
}

// round 4
// speedup vs baseline: 2.7801x; 1.1736x over previous
#include <cuda_runtime.h>
#include <cstdint>
#include <math.h>

#define CC 768
#define NN 256
#define FF 512
#define BATCH 1024
#define ROWS_FINE 4096          // BATCH * 4
#define OUTROW 131073           // 1 + N*F
#define LOGF 6.238324625039508f // log(512)

// ---------------- scratch (no allocations allowed) ----------------
__device__ float g_xn[BATCH * CC];
__device__ float g_xnlo[BATCH * CC];
__device__ float g_buf1[ROWS_FINE * CC];
__device__ float g_buf1lo[BATCH * CC];
__device__ float g_buf2[ROWS_FINE * CC];
__device__ float g_buf2lo[BATCH * CC];
__device__ float g_coarse[BATCH * NN];
__device__ float g_cpart[3 * BATCH * NN];
__device__ int   g_idx[BATCH * 4];
__device__ float g_eln[NN * CC];
__device__ float g_elnW1[NN * CC];
__device__ float g_xnW1[BATCH * CC];
__device__ float g_fine[ROWS_FINE * FF];
__device__ float g_lse[ROWS_FINE];
// pre-rounded weights
__device__ float g_cW1hi[CC * CC], g_cW1lo[CC * CC];
__device__ float g_cW2hi[CC * CC], g_cW2lo[CC * CC];
__device__ float g_cW3hi[CC * NN], g_cW3lo[CC * NN];
__device__ float g_fW1r[2 * CC * CC];
__device__ float g_fW2r[CC * CC];
__device__ float g_fW3r[CC * FF];

__device__ __forceinline__ float gelu_tanh(float x) {
    float x3 = x * x * x;
    return 0.5f * x * (1.0f + tanhf(0.7978845608028654f * (x + 0.044715f * x3)));
}

__device__ __forceinline__ float tf32_rna(float x) {
    float r;
    asm("cvt.rna.tf32.f32 %0, %1;" : "=f"(r) : "f"(x));
    return r;
}

__device__ __forceinline__ void mma8(float* c, const uint32_t* a, const uint32_t* b) {
    asm volatile(
        "mma.sync.aligned.m16n8k8.row.col.f32.tf32.tf32.f32 "
        "{%0,%1,%2,%3}, {%4,%5,%6,%7}, {%8,%9}, {%0,%1,%2,%3};"
        : "+f"(c[0]), "+f"(c[1]), "+f"(c[2]), "+f"(c[3])
        : "r"(a[0]), "r"(a[1]), "r"(a[2]), "r"(a[3]), "r"(b[0]), "r"(b[1]));
}

__device__ __forceinline__ void cp16(void* s, const void* g) {
    uint32_t sa = (uint32_t)__cvta_generic_to_shared(s);
    asm volatile("cp.async.cg.shared.global [%0], [%1], 16;" :: "r"(sa), "l"(g));
}

// ---------------- weight pre-rounding ----------------
__global__ void round_weights(const float* __restrict__ cW1, const float* __restrict__ cW2,
                              const float* __restrict__ cW3, const float* __restrict__ fW1,
                              const float* __restrict__ fW2, const float* __restrict__ fW3) {
    int stride = gridDim.x * blockDim.x;
    int i0 = blockIdx.x * blockDim.x + threadIdx.x;
    for (int i = i0; i < CC * CC; i += stride) {
        float v = cW1[i], h = tf32_rna(v);
        g_cW1hi[i] = h; g_cW1lo[i] = tf32_rna(v - h);
        v = cW2[i]; h = tf32_rna(v);
        g_cW2hi[i] = h; g_cW2lo[i] = tf32_rna(v - h);
        g_fW2r[i] = tf32_rna(fW2[i]);
    }
    for (int i = i0; i < CC * NN; i += stride) {
        float v = cW3[i], h = tf32_rna(v);
        g_cW3hi[i] = h; g_cW3lo[i] = tf32_rna(v - h);
    }
    for (int i = i0; i < 2 * CC * CC; i += stride) g_fW1r[i] = tf32_rna(fW1[i]);
    for (int i = i0; i < CC * FF; i += stride) g_fW3r[i] = tf32_rna(fW3[i]);
}

// ---------------- tf32 tensor-core GEMM, cp.async 3-stage pipeline ----------------
// Operands pre-rounded to tf32. SPLIT_IN: 3-MMA hi/lo for ~fp32 accuracy.
// Split-K via blockIdx.z (kChunk < lda): partial written to C + z*M*N, no bias.
template <int BM, int BN, bool GELU, bool SPLIT_IN, bool SPLIT_OUT, bool ROUND_OUT, bool BIAS>
__global__ void __launch_bounds__(256)
tcgemm(const float* __restrict__ Ahi, const float* __restrict__ Alo,
       const float* __restrict__ Whi, const float* __restrict__ Wlo,
       const float* __restrict__ bias, float* __restrict__ C, float* __restrict__ Clo,
       int M, int N, int lda, int kChunk) {
    constexpr int BK = 16, STAGES = 3;
    constexpr int ASTR = BK + 4;
    constexpr int BSTR = BN + 8;
    constexpr int NSEG = SPLIT_IN ? 2 : 1;
    constexpr int A_ST = BM * ASTR;
    constexpr int B_ST = BK * BSTR;
    constexpr int STW = NSEG * (A_ST + B_ST);
    constexpr int WN_CNT = (BM == 128) ? 2 : 4;
    constexpr int WN = BN / WN_CNT;
    constexpr int NT = WN / 8;
    constexpr int AH = BM / 64;
    constexpr int BH = BN / 64;

    extern __shared__ float smem[];
    const int tid = threadIdx.x;
    const int warp = tid >> 5, lane = tid & 31;
    const int wm = warp / WN_CNT, wn = warp % WN_CNT;
    const int lr = lane >> 2, lc = lane & 3;
    const int m0 = blockIdx.y * BM, n0 = blockIdx.x * BN;
    const int kz = blockIdx.z;
    Ahi += (size_t)kz * kChunk;
    Whi += (size_t)kz * kChunk * N;
    if (SPLIT_IN) { Alo += (size_t)kz * kChunk; Wlo += (size_t)kz * kChunk * N; }
    C += (size_t)kz * M * N;

    float acc[2][NT][4];
#pragma unroll
    for (int mi = 0; mi < 2; mi++)
#pragma unroll
        for (int ni = 0; ni < NT; ni++)
#pragma unroll
            for (int r = 0; r < 4; r++) acc[mi][ni][r] = 0.f;

    const int nk = kChunk / BK;

    auto load_tile = [&](int stg, int k0) {
        float* sA = smem + stg * STW;
        float* sB = sA + NSEG * A_ST;
#pragma unroll
        for (int h = 0; h < AH; h++) {
            int c = tid + h * 256;
            int row = c >> 2, kc = (c & 3) << 2;
            size_t goff = (size_t)(m0 + row) * lda + k0 + kc;
            cp16(sA + row * ASTR + kc, Ahi + goff);
            if (SPLIT_IN) cp16(sA + A_ST + row * ASTR + kc, Alo + goff);
        }
#pragma unroll
        for (int h = 0; h < BH; h++) {
            int c = tid + h * 256;
            int row = c / (BN / 4), col = (c % (BN / 4)) << 2;
            size_t goff = (size_t)(k0 + row) * N + n0 + col;
            cp16(sB + row * BSTR + col, Whi + goff);
            if (SPLIT_IN) cp16(sB + B_ST + row * BSTR + col, Wlo + goff);
        }
    };

    for (int s = 0; s < STAGES - 1; s++) {
        load_tile(s, s * BK);
        asm volatile("cp.async.commit_group;");
    }

    for (int it = 0; it < nk; it++) {
        asm volatile("cp.async.wait_group %0;" :: "n"(STAGES - 2));
        __syncthreads();
        int pre = it + STAGES - 1;
        if (pre < nk) load_tile(pre % STAGES, pre * BK);
        asm volatile("cp.async.commit_group;");

        const float* sA = smem + (it % STAGES) * STW;
        const float* sB = sA + NSEG * A_ST;
#pragma unroll
        for (int ks = 0; ks < 2; ks++) {
            const int kk = ks * 8;
            uint32_t af[NSEG][2][4];
#pragma unroll
            for (int mi = 0; mi < 2; mi++) {
                int mr = wm * 32 + mi * 16 + lr;
#pragma unroll
                for (int s = 0; s < NSEG; s++) {
                    const float* base = sA + s * A_ST;
                    af[s][mi][0] = __float_as_uint(base[mr * ASTR + kk + lc]);
                    af[s][mi][1] = __float_as_uint(base[(mr + 8) * ASTR + kk + lc]);
                    af[s][mi][2] = __float_as_uint(base[mr * ASTR + kk + 4 + lc]);
                    af[s][mi][3] = __float_as_uint(base[(mr + 8) * ASTR + kk + 4 + lc]);
                }
            }
            uint32_t bf[NSEG][NT][2];
#pragma unroll
            for (int ni = 0; ni < NT; ni++) {
                int nc = wn * WN + ni * 8 + lr;
#pragma unroll
                for (int s = 0; s < NSEG; s++) {
                    const float* base = sB + s * B_ST;
                    bf[s][ni][0] = __float_as_uint(base[(kk + lc) * BSTR + nc]);
                    bf[s][ni][1] = __float_as_uint(base[(kk + 4 + lc) * BSTR + nc]);
                }
            }
#pragma unroll
            for (int mi = 0; mi < 2; mi++)
#pragma unroll
                for (int ni = 0; ni < NT; ni++) {
                    mma8(acc[mi][ni], af[0][mi], bf[0][ni]);
                    if (SPLIT_IN) {
                        mma8(acc[mi][ni], af[0][mi], bf[1][ni]);
                        mma8(acc[mi][ni], af[1][mi], bf[0][ni]);
                    }
                }
        }
    }
    asm volatile("cp.async.wait_group 0;");

#pragma unroll
    for (int mi = 0; mi < 2; mi++) {
        int gr = m0 + wm * 32 + mi * 16 + lr;
#pragma unroll
        for (int ni = 0; ni < NT; ni++) {
            int gc = n0 + wn * WN + ni * 8 + (lc << 1);
            float b0v = BIAS ? bias[gc] : 0.f;
            float b1v = BIAS ? bias[gc + 1] : 0.f;
#pragma unroll
            for (int half = 0; half < 2; half++) {
                size_t row = (size_t)(gr + half * 8) * N + gc;
                float v0 = acc[mi][ni][half * 2 + 0] + b0v;
                float v1 = acc[mi][ni][half * 2 + 1] + b1v;
                if (GELU) { v0 = gelu_tanh(v0); v1 = gelu_tanh(v1); }
                if (SPLIT_OUT) {
                    float h0 = tf32_rna(v0), h1 = tf32_rna(v1);
                    float2 hi = {h0, h1};
                    float2 lo = {tf32_rna(v0 - h0), tf32_rna(v1 - h1)};
                    *(float2*)&C[row] = hi;
                    *(float2*)&Clo[row] = lo;
                } else if (ROUND_OUT) {
                    float2 p = {tf32_rna(v0), tf32_rna(v1)};
                    *(float2*)&C[row] = p;
                } else {
                    float2 p = {v0, v1};
                    *(float2*)&C[row] = p;
                }
            }
        }
    }
}

// ---------------- LayerNorm(x) + no_op head (writes tf32 hi/lo) ----------------
__global__ void ln_noop_kernel(const float* __restrict__ x,
                               const float* __restrict__ gin,
                               const float* __restrict__ bin,
                               const float* __restrict__ nW,
                               const float* __restrict__ nb,
                               float* __restrict__ out) {
    int b = blockIdx.x, tid = threadIdx.x;
    const float* xr = x + (size_t)b * CC;
    __shared__ float red[256];
    float v[3];
    float s = 0.f, ss = 0.f;
#pragma unroll
    for (int i = 0; i < 3; i++) {
        v[i] = xr[tid + i * 256];
        s += v[i];
        ss += v[i] * v[i];
    }
    red[tid] = s; __syncthreads();
    for (int o = 128; o > 0; o >>= 1) { if (tid < o) red[tid] += red[tid + o]; __syncthreads(); }
    float mean = red[0] * (1.0f / CC);
    __syncthreads();
    red[tid] = ss; __syncthreads();
    for (int o = 128; o > 0; o >>= 1) { if (tid < o) red[tid] += red[tid + o]; __syncthreads(); }
    float var = red[0] * (1.0f / CC) - mean * mean;
    float rstd = rsqrtf(var + 1e-5f);
    __syncthreads();
    float dot = 0.f;
#pragma unroll
    for (int i = 0; i < 3; i++) {
        int c = tid + i * 256;
        float xn = (v[i] - mean) * rstd * gin[c] + bin[c];
        float h = tf32_rna(xn);
        g_xn[(size_t)b * CC + c] = h;
        g_xnlo[(size_t)b * CC + c] = tf32_rna(xn - h);
        dot += xn * nW[c];
    }
    red[tid] = dot; __syncthreads();
    for (int o = 128; o > 0; o >>= 1) { if (tid < o) red[tid] += red[tid + o]; __syncthreads(); }
    if (tid == 0) out[(size_t)b * OUTROW] = red[0] + nb[0];
}

// ---------------- eln = tf32(LN(emb)) : 256 rows ----------------
__global__ void eln_kernel(const float* __restrict__ emb,
                           const float* __restrict__ ge,
                           const float* __restrict__ be) {
    int n = blockIdx.x, tid = threadIdx.x;
    const float* er = emb + (size_t)n * CC;
    __shared__ float red[256];
    float v[3];
    float s = 0.f, ss = 0.f;
#pragma unroll
    for (int i = 0; i < 3; i++) {
        v[i] = er[tid + i * 256];
        s += v[i];
        ss += v[i] * v[i];
    }
    red[tid] = s; __syncthreads();
    for (int o = 128; o > 0; o >>= 1) { if (tid < o) red[tid] += red[tid + o]; __syncthreads(); }
    float mean = red[0] * (1.0f / CC);
    __syncthreads();
    red[tid] = ss; __syncthreads();
    for (int o = 128; o > 0; o >>= 1) { if (tid < o) red[tid] += red[tid + o]; __syncthreads(); }
    float var = red[0] * (1.0f / CC) - mean * mean;
    float rstd = rsqrtf(var + 1e-5f);
#pragma unroll
    for (int i = 0; i < 3; i++) {
        int c = tid + i * 256;
        g_eln[(size_t)n * CC + c] = tf32_rna((v[i] - mean) * rstd * ge[c] + be[c]);
    }
}

// ---------------- top-4 + split-K reduce (+bias) of coarse logits ----------------
__global__ void top4_reduce_kernel(const float* __restrict__ cb3) {
    int warp = threadIdx.x >> 5, lane = threadIdx.x & 31;
    int row = blockIdx.x * 8 + warp;
    float v[8];
    int id[8];
#pragma unroll
    for (int i = 0; i < 8; i++) {
        int col = lane + i * 32;
        size_t o = (size_t)row * NN + col;
        float s = g_cpart[o] + g_cpart[BATCH * NN + o] + g_cpart[2 * BATCH * NN + o] + cb3[col];
        g_coarse[o] = s;
        v[i] = s;
        id[i] = col;
    }
#pragma unroll
    for (int r = 0; r < 4; r++) {
        float bv = -INFINITY;
        int bi = 1 << 30;
#pragma unroll
        for (int i = 0; i < 8; i++)
            if (v[i] > bv || (v[i] == bv && id[i] < bi)) { bv = v[i]; bi = id[i]; }
        for (int o = 16; o > 0; o >>= 1) {
            float ov = __shfl_xor_sync(0xffffffffu, bv, o);
            int oi = __shfl_xor_sync(0xffffffffu, bi, o);
            if (ov > bv || (ov == bv && oi < bi)) { bv = ov; bi = oi; }
        }
        if (lane == 0) g_idx[row * 4 + r] = bi;
#pragma unroll
        for (int i = 0; i < 8; i++)
            if (id[i] == bi) v[i] = -INFINITY;
    }
}

// ---------------- h1 = tf32(gelu(xnW1a[b] + elnW1b[idx] + fb1)) ----------------
__global__ void combine_kernel(const float* __restrict__ fb1) {
    int b = blockIdx.x, tid = threadIdx.x;
    float xr[3], bb[3];
    int nidx[4];
#pragma unroll
    for (int i = 0; i < 3; i++) {
        xr[i] = g_xnW1[(size_t)b * CC + tid + i * 256];
        bb[i] = fb1[tid + i * 256];
    }
#pragma unroll
    for (int k = 0; k < 4; k++) nidx[k] = g_idx[b * 4 + k];
#pragma unroll
    for (int k = 0; k < 4; k++) {
        float* dst = g_buf1 + (size_t)(b * 4 + k) * CC;
        const float* es = g_elnW1 + (size_t)nidx[k] * CC;
#pragma unroll
        for (int i = 0; i < 3; i++) {
            int c = tid + i * 256;
            dst[c] = tf32_rna(gelu_tanh(xr[i] + es[c] + bb[i]));
        }
    }
}

// ---------------- logsumexp over fine rows ----------------
__global__ void lse_kernel() {
    int r = blockIdx.x, tid = threadIdx.x;
    const float* fr = g_fine + (size_t)r * FF;
    __shared__ float red[256];
    float a = fr[tid], b2 = fr[tid + 256];
    red[tid] = fmaxf(a, b2); __syncthreads();
    for (int o = 128; o > 0; o >>= 1) { if (tid < o) red[tid] = fmaxf(red[tid], red[tid + o]); __syncthreads(); }
    float m = red[0];
    __syncthreads();
    red[tid] = expf(a - m) + expf(b2 - m); __syncthreads();
    for (int o = 128; o > 0; o >>= 1) { if (tid < o) red[tid] += red[tid + o]; __syncthreads(); }
    if (tid == 0) g_lse[r] = m + logf(red[0]);
}

// ---------------- scatter + permute + final write (537 MB, streaming) ----------------
__global__ void output_kernel(float* __restrict__ out) {
    int b = blockIdx.x >> 4;
    int chunk = blockIdx.x & 15;
    int tid = threadIdx.x;
    __shared__ float sc[NN];
    __shared__ int sidx[4];
    __shared__ float slse[4];
    sc[tid] = g_coarse[(size_t)b * NN + tid];
    if (tid < 4) {
        sidx[tid] = g_idx[b * 4 + tid];
        slse[tid] = g_lse[b * 4 + tid];
    }
    __syncthreads();
    size_t obase = (size_t)b * OUTROW + 1;
#pragma unroll 4
    for (int it = 0; it < 32; it++) {
        int o = chunk * 8192 + it * 256 + tid;
        int ch = o >> 13, fh = (o >> 9) & 15, cw = (o >> 5) & 15, j = o & 31;
        int n = (ch << 4) + cw;
        int f = (fh << 5) + j;
        float v = sc[n] - LOGF;
#pragma unroll
        for (int k = 0; k < 4; k++)
            if (sidx[k] == n)
                v = sc[n] + g_fine[(size_t)(b * 4 + k) * FF + f] - slse[k];
        __stcs(&out[obase + o], v);
    }
}

// ---------------- launch ----------------
extern "C" void kernel_launch(void* const* d_in, const int* in_sizes, int n_in,
                              void* d_out, int out_size) {
    (void)in_sizes; (void)n_in; (void)out_size;
    const float* x    = (const float*)d_in[0];
    const float* gin  = (const float*)d_in[1];
    const float* bin  = (const float*)d_in[2];
    const float* cW1  = (const float*)d_in[3];
    const float* cb1  = (const float*)d_in[4];
    const float* cW2  = (const float*)d_in[5];
    const float* cb2  = (const float*)d_in[6];
    const float* cW3  = (const float*)d_in[7];
    const float* cb3  = (const float*)d_in[8];
    const float* emb  = (const float*)d_in[9];
    const float* ge   = (const float*)d_in[10];
    const float* be   = (const float*)d_in[11];
    const float* fW1  = (const float*)d_in[12];
    const float* fb1  = (const float*)d_in[13];
    const float* fW2  = (const float*)d_in[14];
    const float* fb2  = (const float*)d_in[15];
    const float* fW3  = (const float*)d_in[16];
    const float* fb3  = (const float*)d_in[17];
    const float* nW   = (const float*)d_in[18];
    const float* nb   = (const float*)d_in[19];
    float* out = (float*)d_out;

    float *xn, *xnlo, *b1p, *b1lo, *b2p, *b2lo, *coarse, *cpart, *eln, *elnW1, *xnW1, *fine;
    float *cw1h, *cw1l, *cw2h, *cw2l, *cw3h, *cw3l, *fw1r, *fw2r, *fw3r;
    cudaGetSymbolAddress((void**)&xn, g_xn);
    cudaGetSymbolAddress((void**)&xnlo, g_xnlo);
    cudaGetSymbolAddress((void**)&b1p, g_buf1);
    cudaGetSymbolAddress((void**)&b1lo, g_buf1lo);
    cudaGetSymbolAddress((void**)&b2p, g_buf2);
    cudaGetSymbolAddress((void**)&b2lo, g_buf2lo);
    cudaGetSymbolAddress((void**)&coarse, g_coarse);
    cudaGetSymbolAddress((void**)&cpart, g_cpart);
    cudaGetSymbolAddress((void**)&eln, g_eln);
    cudaGetSymbolAddress((void**)&elnW1, g_elnW1);
    cudaGetSymbolAddress((void**)&xnW1, g_xnW1);
    cudaGetSymbolAddress((void**)&fine, g_fine);
    cudaGetSymbolAddress((void**)&cw1h, g_cW1hi);
    cudaGetSymbolAddress((void**)&cw1l, g_cW1lo);
    cudaGetSymbolAddress((void**)&cw2h, g_cW2hi);
    cudaGetSymbolAddress((void**)&cw2l, g_cW2lo);
    cudaGetSymbolAddress((void**)&cw3h, g_cW3hi);
    cudaGetSymbolAddress((void**)&cw3l, g_cW3lo);
    cudaGetSymbolAddress((void**)&fw1r, g_fW1r);
    cudaGetSymbolAddress((void**)&fw2r, g_fW2r);
    cudaGetSymbolAddress((void**)&fw3r, g_fW3r);

    // 3-stage smem sizes
    constexpr int SM_COARSE = 3 * 2 * (64 * 20 + 16 * 72) * 4;   // 58368
    constexpr int SM_FINE   = 3 * (128 * 20 + 16 * 136) * 4;     // 56832
    constexpr int SM_THIN   = 3 * (64 * 20 + 16 * 136) * 4;      // 41472

    auto kCoarseG = tcgemm<64, 64, true,  true,  true,  false, true>;
    auto kCoarseP = tcgemm<64, 64, false, true,  false, false, false>;
    auto kThin    = tcgemm<64, 128, false, false, false, false, false>;
    auto kW2      = tcgemm<128, 128, true,  false, false, true,  true>;
    auto kW3      = tcgemm<128, 128, false, false, false, false, true>;
    cudaFuncSetAttribute((void*)kCoarseG, cudaFuncAttributeMaxDynamicSharedMemorySize, SM_COARSE);
    cudaFuncSetAttribute((void*)kCoarseP, cudaFuncAttributeMaxDynamicSharedMemorySize, SM_COARSE);
    cudaFuncSetAttribute((void*)kThin,    cudaFuncAttributeMaxDynamicSharedMemorySize, SM_THIN);
    cudaFuncSetAttribute((void*)kW2,      cudaFuncAttributeMaxDynamicSharedMemorySize, SM_FINE);
    cudaFuncSetAttribute((void*)kW3,      cudaFuncAttributeMaxDynamicSharedMemorySize, SM_FINE);

    // 0. weight prep + LNs
    round_weights<<<592, 256>>>(cW1, cW2, cW3, fW1, fW2, fW3);
    ln_noop_kernel<<<BATCH, 256>>>(x, gin, bin, nW, nb, out);
    eln_kernel<<<NN, 256>>>(emb, ge, be);

    // 1. coarse MLP (split tf32), W3 split-K=3 -> 192 blocks
    kCoarseG<<<dim3(CC / 64, BATCH / 64), 256, SM_COARSE>>>(
        xn, xnlo, cw1h, cw1l, cb1, b1p, b1lo, BATCH, CC, CC, CC);
    kCoarseG<<<dim3(CC / 64, BATCH / 64), 256, SM_COARSE>>>(
        b1p, b1lo, cw2h, cw2l, cb2, b2p, b2lo, BATCH, CC, CC, CC);
    kCoarseP<<<dim3(NN / 64, BATCH / 64, 3), 256, SM_COARSE>>>(
        b2p, b2lo, cw3h, cw3l, nullptr, cpart, nullptr, BATCH, NN, CC, CC / 3);

    // 2. top-4 (+ reduce partials + bias)
    top4_reduce_kernel<<<BATCH / 8, 256>>>(cb3);

    // 3. fine head, deduped: h1 = gelu(xn@W1a + eln@W1b + b1)
    kThin<<<dim3(CC / 128, BATCH / 64), 256, SM_THIN>>>(
        xn, nullptr, fw1r, nullptr, nullptr, xnW1, nullptr, BATCH, CC, CC, CC);
    kThin<<<dim3(CC / 128, NN / 64), 256, SM_THIN>>>(
        eln, nullptr, fw1r + (size_t)CC * CC, nullptr, nullptr, elnW1, nullptr, NN, CC, CC, CC);
    combine_kernel<<<BATCH, 256>>>(fb1);

    // 4. fine W2, W3
    kW2<<<dim3(CC / 128, ROWS_FINE / 128), 256, SM_FINE>>>(
        b1p, nullptr, fw2r, nullptr, fb2, b2p, nullptr, ROWS_FINE, CC, CC, CC);
    kW3<<<dim3(FF / 128, ROWS_FINE / 128), 256, SM_FINE>>>(
        b2p, nullptr, fw3r, nullptr, fb3, fine, nullptr, ROWS_FINE, FF, CC, CC);

    // 5. logsumexp + output
    lse_kernel<<<ROWS_FINE, 256>>>();
    output_kernel<<<BATCH * 16, 256>>>(out);
}